// round 1
// baseline (speedup 1.0000x reference)
#include <cuda_runtime.h>

#define FULL 0xFFFFFFFFu

__device__ __forceinline__ unsigned long long pack2(float a, float b) {
    unsigned long long r;
    asm("mov.b64 %0, {%1, %2};" : "=l"(r) : "f"(a), "f"(b));
    return r;
}
__device__ __forceinline__ void unpack2(unsigned long long p, float& a, float& b) {
    asm("mov.b64 {%0, %1}, %2;" : "=f"(a), "=f"(b) : "l"(p));
}
__device__ __forceinline__ unsigned long long fma2(unsigned long long a,
                                                   unsigned long long b,
                                                   unsigned long long c) {
    unsigned long long d;
    asm("fma.rn.f32x2 %0, %1, %2, %3;" : "=l"(d) : "l"(a), "l"(b), "l"(c));
    return d;
}
__device__ __forceinline__ unsigned long long add2(unsigned long long a,
                                                   unsigned long long b) {
    unsigned long long d;
    asm("add.rn.f32x2 %0, %1, %2;" : "=l"(d) : "l"(a), "l"(b));
    return d;
}

__device__ __forceinline__ float fast_sigmoid(float x) {
    return __fdividef(1.0f, 1.0f + __expf(-x));
}

// One CTA per batch. Threads 0..255: layer-0 LSTM (thread t owns gate column
// g*64+u, weights register-resident, f32x2 packed FMA). Threads 256..287
// (warp 8): layer-1 LSTM (units=1) + dense, running one step lagged so it
// overlaps with layer-0's next-step dot product. One __syncthreads per step.
__global__ __launch_bounds__(288, 2)
void lstm_stack_kernel(const float* __restrict__ x,
                       const float* __restrict__ W0,
                       const float* __restrict__ b0,
                       const float* __restrict__ W1,
                       const float* __restrict__ b1,
                       const float* __restrict__ Wd,
                       const float* __restrict__ bd,
                       float* __restrict__ out)
{
    constexpr int T = 2048;

    const int bb   = blockIdx.x;
    const int tid  = threadIdx.x;
    const int lane = tid & 31;
    const int wid  = tid >> 5;

    __shared__ __align__(16) float x_sh[T];
    __shared__ __align__(16) float h_sh[2][64];
    __shared__ float red[9];
    __shared__ float inv_sh;

    // ---- Phase 0: load x tile, l2-normalize over time ----
    const float* xb = x + bb * T;
    float ps = 0.f;
    for (int i = tid; i < T; i += 288) {
        float v = xb[i];
        x_sh[i] = v;
        ps = fmaf(v, v, ps);
    }
    #pragma unroll
    for (int o = 16; o > 0; o >>= 1) ps += __shfl_xor_sync(FULL, ps, o);
    if (lane == 0) red[wid] = ps;
    if (tid < 64) h_sh[0][tid] = 0.f;   // h_{-1} = 0
    __syncthreads();
    if (tid == 0) {
        float s = 0.f;
        #pragma unroll
        for (int i = 0; i < 9; ++i) s += red[i];
        inv_sh = rsqrtf(fmaxf(s, 1e-12f));
    }
    __syncthreads();
    {
        float inv = inv_sh;
        for (int i = tid; i < T; i += 288) x_sh[i] *= inv;
    }
    // (ordered by the sync at the top of the main loop)

    // ---- Per-thread persistent state / weights ----
    const int g = tid & 3;      // gate: 0=i 1=j 2=f 3=o
    const int u = tid >> 2;     // unit 0..63
    unsigned long long wp[32];  // layer-0 column weights, packed f32x2
    float wx = 0.f, b0v = 0.f;
    float c0 = 0.f;

    // layer-1 (warp 8) state
    const int l1g  = lane & 3;
    const int l1bk = lane >> 2;
    float w1r[8];
    float w1h = 0.f, b1v = 0.f, wdv = 0.f, bdv = 0.f;
    float c1 = 0.f, h1 = 0.f;

    if (tid < 256) {
        const int col = g * 64 + u;
        wx  = W0[col];        // row 0: x weight
        b0v = b0[col];
        #pragma unroll
        for (int p = 0; p < 32; ++p) {
            float a  = W0[(1 + 2 * p) * 256 + col];
            float bv = W0[(2 + 2 * p) * 256 + col];
            wp[p] = pack2(a, bv);
        }
    } else {
        #pragma unroll
        for (int j = 0; j < 8; ++j)
            w1r[j] = W1[(l1bk + 8 * j) * 4 + l1g];
        w1h = W1[64 * 4 + l1g];
        b1v = b1[l1g];
        wdv = Wd[0];
        bdv = bd[0];
    }

    float* outb = out + bb * T;

    // ---- Main recurrence: t = 0..T. Layer-0 active for t<T, layer-1
    // processes step t-1 (so the final iteration drains layer-1). ----
    #pragma unroll 1
    for (int t = 0; t <= T; ++t) {
        __syncthreads();                 // h_sh[t&1] = h_{t-1} now valid
        const int cur = t & 1;
        if (tid < 256) {
            if (t < T) {
                float xt = x_sh[t];
                const float4* hp = (const float4*)h_sh[cur];
                unsigned long long a0, a1, a2, a3;
                a0 = a1 = a2 = a3 = pack2(0.f, 0.f);
                #pragma unroll
                for (int i = 0; i < 16; ++i) {
                    float4 hv = hp[i];
                    unsigned long long h01 = pack2(hv.x, hv.y);
                    unsigned long long h23 = pack2(hv.z, hv.w);
                    if (i & 1) { a2 = fma2(h01, wp[2*i], a2); a3 = fma2(h23, wp[2*i+1], a3); }
                    else       { a0 = fma2(h01, wp[2*i], a0); a1 = fma2(h23, wp[2*i+1], a1); }
                }
                unsigned long long s01 = add2(add2(a0, a1), add2(a2, a3));
                float slo, shi; unpack2(s01, slo, shi);
                float z = fmaf(xt, wx, b0v) + slo + shi;

                // branch-free gate nonlinearity: tanh(x) = 2*sigmoid(2x)-1
                float zz = (g == 2) ? (z + 1.0f) : z;   // forget bias
                float sv = (g == 1) ? (zz + zz) : zz;
                float sg = fast_sigmoid(sv);
                float r  = (g == 1) ? (2.f * sg - 1.f) : sg;

                float ri = __shfl_sync(FULL, r, 0, 4);
                float rj = __shfl_sync(FULL, r, 1, 4);
                float rf = __shfl_sync(FULL, r, 2, 4);
                float ro = __shfl_sync(FULL, r, 3, 4);
                c0 = fmaf(rf, c0, ri * rj);             // redundant in 4 lanes (bitwise identical)
                float th = 2.f * fast_sigmoid(c0 + c0) - 1.f;
                float h  = ro * th;
                if (g == 0) h_sh[cur ^ 1][u] = h;
            }
        } else {
            if (t >= 1) {
                // layer-1 for step s = t-1, input h_sh[cur] = h^{(0)}_{t-1}
                const float* hv = h_sh[cur];
                float p = 0.f;
                #pragma unroll
                for (int j = 0; j < 8; ++j)
                    p = fmaf(hv[l1bk + 8 * j], w1r[j], p);
                p += __shfl_xor_sync(FULL, p, 4);
                p += __shfl_xor_sync(FULL, p, 8);
                p += __shfl_xor_sync(FULL, p, 16);
                float z1 = fmaf(h1, w1h, p + b1v);

                float zz = (l1g == 2) ? (z1 + 1.0f) : z1;
                float sv = (l1g == 1) ? (zz + zz) : zz;
                float sg = fast_sigmoid(sv);
                float r  = (l1g == 1) ? (2.f * sg - 1.f) : sg;

                float ri = __shfl_sync(FULL, r, 0, 4);
                float rj = __shfl_sync(FULL, r, 1, 4);
                float rf = __shfl_sync(FULL, r, 2, 4);
                float ro = __shfl_sync(FULL, r, 3, 4);
                c1 = fmaf(rf, c1, ri * rj);
                float th = 2.f * fast_sigmoid(c1 + c1) - 1.f;
                h1 = ro * th;
                if (lane == 0) outb[t - 1] = fmaf(h1, wdv, bdv);
            }
        }
    }
}

extern "C" void kernel_launch(void* const* d_in, const int* in_sizes, int n_in,
                              void* d_out, int out_size) {
    const float* x  = (const float*)d_in[0];
    const float* W0 = (const float*)d_in[1];
    const float* b0 = (const float*)d_in[2];
    const float* W1 = (const float*)d_in[3];
    const float* b1 = (const float*)d_in[4];
    const float* Wd = (const float*)d_in[5];
    const float* bd = (const float*)d_in[6];
    float* out = (float*)d_out;
    lstm_stack_kernel<<<256, 288>>>(x, W0, b0, W1, b1, Wd, bd, out);
}